// round 16
// baseline (speedup 1.0000x reference)
#include <cuda_runtime.h>
#include <cstdint>

// KVGather: out[n,i,k,w,c] = r_weight[n,i,k] * kv[n, r_idx[n,i,k], w, c]
// N=16, P2=64, TOPK=8, W2=64, C_KV=512
//
// Champion (R5/R13/R14/R15): 128-bit __ldg + __stcs, 256thr x 2048f4 blocks,
// kernel 173.7-174.9 us over 5 runs at the compulsory traffic floor.
// R16 — FINAL UNTESTED AXIS PROBE: __stwt (st.global.wt) write-through
// stores instead of __stcs. Hypothesis: skip L2 write-line allocation churn
// for the 1 GiB stream, freeing LTS slots/tags for the kv read stream.
// If neutral/worse, revert to champion and the search is exhausted.

#define KVG_N     16
#define KVG_P2    64
#define KVG_TOPK  8
#define KVG_W2    64
#define KVG_CKV   512

#define NUM_TILES   (KVG_N * KVG_P2 * KVG_TOPK)      // 8192
#define TILE_F4     (KVG_W2 * KVG_CKV / 4)           // 8192 float4 per tile (128 KB)
#define F4_PER_THR  8
#define THREADS     256
#define F4_PER_BLK  (F4_PER_THR * THREADS)           // 2048
#define BLKS_PER_TILE (TILE_F4 / F4_PER_BLK)         // 4
#define GRID        (NUM_TILES * BLKS_PER_TILE)      // 32768

__global__ __launch_bounds__(THREADS, 8)
void kvg_gather_kernel(const float4* __restrict__ kv,
                       const float*  __restrict__ r_weight,
                       const void*   __restrict__ r_idx,
                       float4*       __restrict__ out) {
    const int bid   = blockIdx.x;
    const int tile  = bid >> 2;            // BLKS_PER_TILE = 4
    const int chunk = bid & 3;
    const int n     = tile >> 9;           // / (P2*TOPK)

    // ---- int64-vs-int32 index-width detection, fused in-kernel ----
    // View r_idx as int32 words. int64 values in [0,64) -> every odd word 0.
    // int32 indices -> OR of 32 odd words nonzero w.p. 1-(1/64)^32.
    // Words [1..63] are in-bounds for both layouts; sectors are L2-hot.
    const int lane = threadIdx.x & 31;
    unsigned probe = ((const unsigned*)r_idx)[2 * lane + 1];
    unsigned odd_or = __reduce_or_sync(0xffffffffu, probe);
    const bool is64 = (odd_or == 0u);

    long long idx;
    if (is64) idx = ((const long long*)r_idx)[tile];
    else      idx = (long long)((const int*)r_idx)[tile];

    const float wt = r_weight[tile];

    const float4* __restrict__ src =
        kv + ((long long)n * KVG_P2 + idx) * (long long)TILE_F4;
    float4* __restrict__ dst = out + (long long)tile * (long long)TILE_F4;

    const int base = chunk * F4_PER_BLK + threadIdx.x;

#pragma unroll
    for (int j = 0; j < F4_PER_THR; j++) {
        const int p = base + j * THREADS;
        float4 v = __ldg(&src[p]);
        v.x *= wt; v.y *= wt; v.z *= wt; v.w *= wt;
        // A/B probe: write-through store — no L2 write-line allocation for
        // the write-once 1 GiB stream.
        __stwt(&dst[p], v);
    }
}

extern "C" void kernel_launch(void* const* d_in, const int* in_sizes, int n_in,
                              void* d_out, int out_size) {
    // metadata order: r_idx, r_weight, kv
    const void*  r_idx    = d_in[0];
    const float* r_weight = (const float*)d_in[1];
    const float4* kv      = (const float4*)d_in[2];
    float4* out           = (float4*)d_out;

    kvg_gather_kernel<<<GRID, THREADS>>>(kv, r_weight, r_idx, out);
}

// round 17
// speedup vs baseline: 1.0219x; 1.0219x over previous
#include <cuda_runtime.h>
#include <cstdint>

// KVGather: out[n,i,k,w,c] = r_weight[n,i,k] * kv[n, r_idx[n,i,k], w, c]
// N=16, P2=64, TOPK=8, W2=64, C_KV=512
//
// FINAL CHAMPION — locked after a 16-round exhaustive A/B sweep.
// Kernel 173.7-174.9 us over 5 runs (sigma <0.5%), 6570-6630 GB/s, DRAM
// ~83%. At the compulsory traffic floor: 1.149 GB measured DRAM traffic
// (1.074 GiB write + partial kv read spill; L2 retains the rest) vs
// 1.202 GB naive minimum. Time floor = traffic / achievable BW ~ 174 us;
// the kernel measures exactly that.
//
// Axis sweep results (all measured, each regression diagnosed):
//  - Load width: 128-bit __ldg wins. 256-bit loads serialize in L1tex
//    (R4: -37%, L1 82%).
//  - Load L2 policy: plain wins. createpolicy/L2::cache_hint evict_last is
//    bimodal across runs (R8 173us, R12 240us w/ L1tex spike) -> rejected
//    on reproducibility despite best single run.
//  - Store policy: __stcs (evict-first streaming) wins over default (R7,
//    +2.3us), write-through __stwt (R16, +3.5us), and STG.256 (R9, neutral).
//  - Block shape: 256-thread one-shot blocks, 2048 float4 each (32768
//    blocks) win over 128-thread (R11, +2us), tile-per-block (R10, +10us),
//    persistent grid (R6, +68us). HW scheduler pipelines fresh blocks'
//    front-batched loads against draining stores across block boundaries.
//  - Launch structure: int64/int32 index-width detection fused in-kernel
//    (warp-probe of odd words, L2-hot) saves the ~5us detect launch.

#define KVG_N     16
#define KVG_P2    64
#define KVG_TOPK  8
#define KVG_W2    64
#define KVG_CKV   512

#define NUM_TILES   (KVG_N * KVG_P2 * KVG_TOPK)      // 8192
#define TILE_F4     (KVG_W2 * KVG_CKV / 4)           // 8192 float4 per tile (128 KB)
#define F4_PER_THR  8
#define THREADS     256
#define F4_PER_BLK  (F4_PER_THR * THREADS)           // 2048
#define BLKS_PER_TILE (TILE_F4 / F4_PER_BLK)         // 4
#define GRID        (NUM_TILES * BLKS_PER_TILE)      // 32768

__global__ __launch_bounds__(THREADS, 8)
void kvg_gather_kernel(const float4* __restrict__ kv,
                       const float*  __restrict__ r_weight,
                       const void*   __restrict__ r_idx,
                       float4*       __restrict__ out) {
    const int bid   = blockIdx.x;
    const int tile  = bid >> 2;            // BLKS_PER_TILE = 4
    const int chunk = bid & 3;
    const int n     = tile >> 9;           // / (P2*TOPK)

    // ---- int64-vs-int32 index-width detection, fused in-kernel ----
    // View r_idx as int32 words. int64 values in [0,64) -> every odd word 0.
    // int32 indices -> OR of 32 odd words nonzero w.p. 1-(1/64)^32.
    // Words [1..63] are in-bounds for both layouts; sectors are L2-hot.
    const int lane = threadIdx.x & 31;
    unsigned probe = ((const unsigned*)r_idx)[2 * lane + 1];
    unsigned odd_or = __reduce_or_sync(0xffffffffu, probe);
    const bool is64 = (odd_or == 0u);

    long long idx;
    if (is64) idx = ((const long long*)r_idx)[tile];
    else      idx = (long long)((const int*)r_idx)[tile];

    const float wt = r_weight[tile];

    const float4* __restrict__ src =
        kv + ((long long)n * KVG_P2 + idx) * (long long)TILE_F4;
    float4* __restrict__ dst = out + (long long)tile * (long long)TILE_F4;

    const int base = chunk * F4_PER_BLK + threadIdx.x;

#pragma unroll
    for (int j = 0; j < F4_PER_THR; j++) {
        const int p = base + j * THREADS;
        float4 v = __ldg(&src[p]);
        v.x *= wt; v.y *= wt; v.z *= wt; v.w *= wt;
        // Streaming store: evict-first write stream keeps the hot kv read
        // set resident in L2.
        __stcs(&dst[p], v);
    }
}

extern "C" void kernel_launch(void* const* d_in, const int* in_sizes, int n_in,
                              void* d_out, int out_size) {
    // metadata order: r_idx, r_weight, kv
    const void*  r_idx    = d_in[0];
    const float* r_weight = (const float*)d_in[1];
    const float4* kv      = (const float4*)d_in[2];
    float4* out           = (float4*)d_out;

    kvg_gather_kernel<<<GRID, THREADS>>>(kv, r_weight, r_idx, out);
}